// round 2
// baseline (speedup 1.0000x reference)
#include <cuda_runtime.h>
#include <cuda_bf16.h>

#define BATCH 16
#define NPTS  8192
#define NSAMP 4096
#define THREADS 1024
#define PPT 8   // points per thread = NPTS / THREADS

// FPS-selected indices, produced by fps_kernel, consumed by gather_kernel.
__device__ int g_idx[BATCH * NSAMP];

__global__ __launch_bounds__(THREADS, 1)
void fps_kernel(const float* __restrict__ coords, const int* __restrict__ init_farthest)
{
    const int b = blockIdx.x;
    const int t = threadIdx.x;
    const int base = t * PPT;

    const float* cb = coords + (size_t)b * NPTS * 3;

    // Per-thread point data lives entirely in registers.
    float px[PPT], py[PPT], pz[PPT], dist[PPT];
#pragma unroll
    for (int j = 0; j < PPT; j++) {
        px[j] = cb[(base + j) * 3 + 0];
        py[j] = cb[(base + j) * 3 + 1];
        pz[j] = cb[(base + j) * 3 + 2];
        dist[j] = 1e8f;   // INIT_DIST
    }

    __shared__ float s_cx, s_cy, s_cz;
    __shared__ float s_wd[32];
    __shared__ int   s_wi[32];
    __shared__ int   s_f;

    int f = init_farthest[b];
    if (f >= base && f < base + PPT) {
        s_cx = px[f - base];
        s_cy = py[f - base];
        s_cz = pz[f - base];
    }
    __syncthreads();

    int* gout = g_idx + b * NSAMP;

    for (int s = 0; s < NSAMP; s++) {
        // Emit the centroid index used this step (reference records then updates).
        if (t == 0) gout[s] = f;

        const float cx = s_cx, cy = s_cy, cz = s_cz;

        float bd = -1.0f;
        int   bi = 0;
#pragma unroll
        for (int j = 0; j < PPT; j++) {
            float dx = px[j] - cx;
            float dy = py[j] - cy;
            float dz = pz[j] - cz;
            // Match XLA lowering: sequential reduce with FMA contraction:
            // ((0 + dx*dx) + dy*dy) + dz*dz  ->  fma chain
            float d = __fmaf_rn(dz, dz, __fmaf_rn(dy, dy, __fmaf_rn(dx, dx, 0.0f)));
            float nd = fminf(dist[j], d);
            dist[j] = nd;
            // strict > keeps the lowest index within this thread (ascending j)
            if (nd > bd) { bd = nd; bi = base + j; }
        }

        // Warp-level argmax with lowest-index tie-break.
        const unsigned m = 0xffffffffu;
#pragma unroll
        for (int o = 16; o > 0; o >>= 1) {
            float od = __shfl_down_sync(m, bd, o);
            int   oi = __shfl_down_sync(m, bi, o);
            if (od > bd || (od == bd && oi < bi)) { bd = od; bi = oi; }
        }
        const int w = t >> 5, l = t & 31;
        if (l == 0) { s_wd[w] = bd; s_wi[w] = bi; }
        __syncthreads();

        if (w == 0) {
            bd = s_wd[l];
            bi = s_wi[l];
#pragma unroll
            for (int o = 16; o > 0; o >>= 1) {
                float od = __shfl_down_sync(m, bd, o);
                int   oi = __shfl_down_sync(m, bi, o);
                if (od > bd || (od == bd && oi < bi)) { bd = od; bi = oi; }
            }
            if (l == 0) s_f = bi;
        }
        __syncthreads();

        f = s_f;
        // Owner of the winning point publishes the new centroid.
        const int j = f - base;
        if (j >= 0 && j < PPT) {
            s_cx = px[j]; s_cy = py[j]; s_cz = pz[j];
        }
        __syncthreads();
    }
}

// Output layout: [B,S,3] coords | [B,S,128] values | [B,S] mask, all fp32, concatenated.
__global__ void gather_kernel(const float* __restrict__ coords,
                              const float* __restrict__ values,
                              const float* __restrict__ mask,
                              float* __restrict__ out)
{
    const int V4 = BATCH * NSAMP * 32;   // float4 chunks of values output
    int i = blockIdx.x * blockDim.x + threadIdx.x;

    float* out_coords = out;                                   // B*S*3
    float* out_vals   = out + (size_t)BATCH * NSAMP * 3;       // B*S*128
    float* out_mask   = out + (size_t)BATCH * NSAMP * (3 + 128);

    if (i < V4) {
        const int c4 = i & 31;
        const int bs = i >> 5;
        const int b  = bs >> 12;            // / NSAMP
        const int s  = bs & (NSAMP - 1);
        const int idx = g_idx[b * NSAMP + s];
        const float4 v = reinterpret_cast<const float4*>(values)
                             [((size_t)b * NPTS + idx) * 32 + c4];
        reinterpret_cast<float4*>(out_vals)[(size_t)bs * 32 + c4] = v;
    } else if (i < V4 + BATCH * NSAMP) {
        const int bs = i - V4;
        const int b  = bs >> 12;
        const int s  = bs & (NSAMP - 1);
        const int idx = g_idx[b * NSAMP + s];
        const size_t src = (size_t)b * NPTS + idx;
        out_coords[bs * 3 + 0] = coords[src * 3 + 0];
        out_coords[bs * 3 + 1] = coords[src * 3 + 1];
        out_coords[bs * 3 + 2] = coords[src * 3 + 2];
        out_mask[bs] = mask[src];
    }
}

extern "C" void kernel_launch(void* const* d_in, const int* in_sizes, int n_in,
                              void* d_out, int out_size)
{
    const float* coords = (const float*)d_in[0];
    const float* values = (const float*)d_in[1];
    const float* mask   = (const float*)d_in[2];
    const int*   initf  = (const int*)d_in[3];
    float* out = (float*)d_out;

    fps_kernel<<<BATCH, THREADS>>>(coords, initf);

    const int total = BATCH * NSAMP * 32 + BATCH * NSAMP;
    gather_kernel<<<(total + 255) / 256, 256>>>(coords, values, mask, out);
}

// round 3
// speedup vs baseline: 1.6011x; 1.6011x over previous
#include <cuda_runtime.h>
#include <cuda_bf16.h>

#define BATCH 16
#define NPTS  8192
#define NSAMP 4096
#define THREADS 512
#define PPT 16            // points per thread = NPTS / THREADS
#define NPAIR (PPT / 2)

typedef unsigned long long u64;

__device__ int g_idx[BATCH * NSAMP];

// ---------- packed f32x2 helpers (per-lane IEEE rn => bit-identical to scalar) ----------
__device__ __forceinline__ u64 pack2(float lo, float hi) {
    u64 r; asm("mov.b64 %0, {%1, %2};" : "=l"(r) : "f"(lo), "f"(hi)); return r;
}
__device__ __forceinline__ void unpack2(u64 v, float& lo, float& hi) {
    asm("mov.b64 {%0, %1}, %2;" : "=f"(lo), "=f"(hi) : "l"(v));
}
__device__ __forceinline__ u64 add2(u64 a, u64 b) {
    u64 r; asm("add.rn.f32x2 %0, %1, %2;" : "=l"(r) : "l"(a), "l"(b)); return r;
}
__device__ __forceinline__ u64 mul2(u64 a, u64 b) {
    u64 r; asm("mul.rn.f32x2 %0, %1, %2;" : "=l"(r) : "l"(a), "l"(b)); return r;
}
__device__ __forceinline__ u64 fma2(u64 a, u64 b, u64 c) {
    u64 r; asm("fma.rn.f32x2 %0, %1, %2, %3;" : "=l"(r) : "l"(a), "l"(b), "l"(c)); return r;
}
__device__ __forceinline__ unsigned redux_max_u32(unsigned v) {
    unsigned r; asm("redux.sync.max.u32 %0, %1, 0xffffffff;" : "=r"(r) : "r"(v)); return r;
}
__device__ __forceinline__ unsigned redux_min_u32(unsigned v) {
    unsigned r; asm("redux.sync.min.u32 %0, %1, 0xffffffff;" : "=r"(r) : "r"(v)); return r;
}

struct SmemLayout {
    float4 pts[NPTS];   // 128 KB: coords copy for centroid broadcast
    u64    key[3];      // triple-buffered (dist_bits<<32 | ~idx) argmax keys
};

__global__ __launch_bounds__(THREADS, 1)
void fps_kernel(const float* __restrict__ coords, const int* __restrict__ init_farthest)
{
    extern __shared__ char raw[];
    SmemLayout* sm = reinterpret_cast<SmemLayout*>(raw);

    const int b = blockIdx.x;
    const int t = threadIdx.x;
    const int base = t * PPT;
    const float* cb = coords + (size_t)b * NPTS * 3;

    // ---- init: populate shared coords copy + packed register copies ----
    float lx[PPT], ly[PPT], lz[PPT];
#pragma unroll
    for (int j = 0; j < PPT; j++) {
        const int idx = base + j;
        lx[j] = cb[idx * 3 + 0];
        ly[j] = cb[idx * 3 + 1];
        lz[j] = cb[idx * 3 + 2];
        sm->pts[idx] = make_float4(lx[j], ly[j], lz[j], 0.0f);
    }
    u64 PX[NPAIR], PY[NPAIR], PZ[NPAIR];
    float dist[PPT];
#pragma unroll
    for (int p = 0; p < NPAIR; p++) {
        PX[p] = pack2(lx[2 * p], lx[2 * p + 1]);
        PY[p] = pack2(ly[2 * p], ly[2 * p + 1]);
        PZ[p] = pack2(lz[2 * p], lz[2 * p + 1]);
    }
#pragma unroll
    for (int j = 0; j < PPT; j++) dist[j] = 1e8f;   // INIT_DIST

    if (t == 0) { sm->key[0] = 0; sm->key[1] = 0; sm->key[2] = 0; }

    int f = init_farthest[b];
    __syncthreads();

    int* gout = g_idx + b * NSAMP;
    int s3 = 0;                 // s % 3
    const int lane = t & 31;

    for (int s = 0; s < NSAMP; s++) {
        if (t == 0) gout[s] = f;   // record current farthest (torch/jax: record then update)

        const float4 c = sm->pts[f];
        const u64 ncx = pack2(-c.x, -c.x);
        const u64 ncy = pack2(-c.y, -c.y);
        const u64 ncz = pack2(-c.z, -c.z);

        float bd = -1.0f;
#pragma unroll
        for (int p = 0; p < NPAIR; p++) {
            u64 dx = add2(PX[p], ncx);
            u64 dy = add2(PY[p], ncy);
            u64 dz = add2(PZ[p], ncz);
            // d = fma(dz,dz, fma(dy,dy, dx*dx)) per lane — matches XLA's contracted reduce
            u64 d2 = fma2(dz, dz, fma2(dy, dy, mul2(dx, dx)));
            float d0, d1; unpack2(d2, d0, d1);
            float n0 = fminf(dist[2 * p], d0);
            float n1 = fminf(dist[2 * p + 1], d1);
            dist[2 * p] = n0;
            dist[2 * p + 1] = n1;
            bd = fmaxf(bd, n0);
            bd = fmaxf(bd, n1);
        }
        // recover lowest local index achieving bd (reverse scan -> lowest j wins)
        int bj = 0;
#pragma unroll
        for (int j = PPT - 1; j >= 0; j--) if (dist[j] == bd) bj = j;
        const int bi = base + bj;

        // warp argmax: value via redux-max on bits (dists >= 0 => monotonic),
        // then lowest index among lanes holding the max
        const unsigned vb = __float_as_uint(bd);
        const unsigned wmax = redux_max_u32(vb);
        const unsigned cand = (vb == wmax) ? (unsigned)bi : 0xFFFFFFFFu;
        const unsigned wbi = redux_min_u32(cand);

        if (lane == 0) {
            const u64 key = ((u64)wmax << 32) | (u64)(~wbi);
            atomicMax(&sm->key[s3], key);
        }
        __syncthreads();

        const u64 k = sm->key[s3];
        f = (int)(~(unsigned)k);

        // zero the buffer two steps ahead (safe: its readers finished pre-bar(s))
        if (t == 0) sm->key[s3 == 0 ? 2 : s3 - 1] = 0;
        s3 = (s3 == 2) ? 0 : s3 + 1;
    }
}

// Output layout: [B,S,3] coords | [B,S,128] values | [B,S] mask, all fp32, concatenated.
__global__ void gather_kernel(const float* __restrict__ coords,
                              const float* __restrict__ values,
                              const float* __restrict__ mask,
                              float* __restrict__ out)
{
    const int V4 = BATCH * NSAMP * 32;   // float4 chunks of values output
    int i = blockIdx.x * blockDim.x + threadIdx.x;

    float* out_coords = out;
    float* out_vals   = out + (size_t)BATCH * NSAMP * 3;
    float* out_mask   = out + (size_t)BATCH * NSAMP * (3 + 128);

    if (i < V4) {
        const int c4 = i & 31;
        const int bs = i >> 5;
        const int b  = bs >> 12;
        const int s  = bs & (NSAMP - 1);
        const int idx = g_idx[b * NSAMP + s];
        const float4 v = reinterpret_cast<const float4*>(values)
                             [((size_t)b * NPTS + idx) * 32 + c4];
        reinterpret_cast<float4*>(out_vals)[(size_t)bs * 32 + c4] = v;
    } else if (i < V4 + BATCH * NSAMP) {
        const int bs = i - V4;
        const int b  = bs >> 12;
        const int s  = bs & (NSAMP - 1);
        const int idx = g_idx[b * NSAMP + s];
        const size_t src = (size_t)b * NPTS + idx;
        out_coords[bs * 3 + 0] = coords[src * 3 + 0];
        out_coords[bs * 3 + 1] = coords[src * 3 + 1];
        out_coords[bs * 3 + 2] = coords[src * 3 + 2];
        out_mask[bs] = mask[src];
    }
}

extern "C" void kernel_launch(void* const* d_in, const int* in_sizes, int n_in,
                              void* d_out, int out_size)
{
    const float* coords = (const float*)d_in[0];
    const float* values = (const float*)d_in[1];
    const float* mask   = (const float*)d_in[2];
    const int*   initf  = (const int*)d_in[3];
    float* out = (float*)d_out;

    const int smem = sizeof(SmemLayout);
    cudaFuncSetAttribute(fps_kernel, cudaFuncAttributeMaxDynamicSharedMemorySize, smem);

    fps_kernel<<<BATCH, THREADS, smem>>>(coords, initf);

    const int total = BATCH * NSAMP * 32 + BATCH * NSAMP;
    gather_kernel<<<(total + 255) / 256, 256>>>(coords, values, mask, out);
}

// round 4
// speedup vs baseline: 2.1088x; 1.3171x over previous
#include <cuda_runtime.h>
#include <cuda_bf16.h>

#define BATCH 16
#define NPTS  8192
#define NSAMP 4096
#define THREADS 512
#define PPT 16            // points per thread = NPTS / THREADS
#define NPAIR (PPT / 2)
#define NWARP (THREADS / 32)

typedef unsigned long long u64;

__device__ int g_idx[BATCH * NSAMP];

// ---------- packed f32x2 helpers (per-lane IEEE rn => bit-identical to scalar) ----------
__device__ __forceinline__ u64 pack2(float lo, float hi) {
    u64 r; asm("mov.b64 %0, {%1, %2};" : "=l"(r) : "f"(lo), "f"(hi)); return r;
}
__device__ __forceinline__ void unpack2(u64 v, float& lo, float& hi) {
    asm("mov.b64 {%0, %1}, %2;" : "=f"(lo), "=f"(hi) : "l"(v));
}
__device__ __forceinline__ u64 add2(u64 a, u64 b) {
    u64 r; asm("add.rn.f32x2 %0, %1, %2;" : "=l"(r) : "l"(a), "l"(b)); return r;
}
__device__ __forceinline__ u64 mul2(u64 a, u64 b) {
    u64 r; asm("mul.rn.f32x2 %0, %1, %2;" : "=l"(r) : "l"(a), "l"(b)); return r;
}
__device__ __forceinline__ u64 fma2(u64 a, u64 b, u64 c) {
    u64 r; asm("fma.rn.f32x2 %0, %1, %2, %3;" : "=l"(r) : "l"(a), "l"(b), "l"(c)); return r;
}
__device__ __forceinline__ unsigned redux_max_u32(unsigned v) {
    unsigned r; asm("redux.sync.max.u32 %0, %1, 0xffffffff;" : "=r"(r) : "r"(v)); return r;
}
__device__ __forceinline__ unsigned redux_min_u32(unsigned v) {
    unsigned r; asm("redux.sync.min.u32 %0, %1, 0xffffffff;" : "=r"(r) : "r"(v)); return r;
}

struct SmemLayout {
    float4 pts[NPTS];        // 128 KB: coords copy for centroid broadcast
    u64    key[2][NWARP];    // double-buffered per-warp argmax keys (dist_bits<<32 | idx)
};

__global__ __launch_bounds__(THREADS, 1)
void fps_kernel(const float* __restrict__ coords, const int* __restrict__ init_farthest)
{
    extern __shared__ char raw[];
    SmemLayout* sm = reinterpret_cast<SmemLayout*>(raw);

    const int b = blockIdx.x;
    const int t = threadIdx.x;
    const int base = t * PPT;
    const float* cb = coords + (size_t)b * NPTS * 3;

    // ---- init: populate shared coords copy + packed register copies ----
    float lx[PPT], ly[PPT], lz[PPT];
#pragma unroll
    for (int j = 0; j < PPT; j++) {
        const int idx = base + j;
        lx[j] = cb[idx * 3 + 0];
        ly[j] = cb[idx * 3 + 1];
        lz[j] = cb[idx * 3 + 2];
        sm->pts[idx] = make_float4(lx[j], ly[j], lz[j], 0.0f);
    }
    u64 PX[NPAIR], PY[NPAIR], PZ[NPAIR];
    float dist[PPT];
#pragma unroll
    for (int p = 0; p < NPAIR; p++) {
        PX[p] = pack2(lx[2 * p], lx[2 * p + 1]);
        PY[p] = pack2(ly[2 * p], ly[2 * p + 1]);
        PZ[p] = pack2(lz[2 * p], lz[2 * p + 1]);
    }
#pragma unroll
    for (int j = 0; j < PPT; j++) dist[j] = 1e8f;   // INIT_DIST

    int f = init_farthest[b];
    __syncthreads();

    int* gout = g_idx + b * NSAMP;
    const int lane = t & 31;
    const int w = t >> 5;
    int par = 0;

    for (int s = 0; s < NSAMP; s++) {
        if (t == 0) gout[s] = f;   // record current farthest (record then update)

        const float4 c = sm->pts[f];
        const u64 ncx = pack2(-c.x, -c.x);
        const u64 ncy = pack2(-c.y, -c.y);
        const u64 ncz = pack2(-c.z, -c.z);

        float bd = -1.0f;
#pragma unroll
        for (int p = 0; p < NPAIR; p++) {
            u64 dx = add2(PX[p], ncx);
            u64 dy = add2(PY[p], ncy);
            u64 dz = add2(PZ[p], ncz);
            // per-lane d = fma(dz,dz, fma(dy,dy, dx*dx)) — matches XLA contracted reduce
            u64 d2 = fma2(dz, dz, fma2(dy, dy, mul2(dx, dx)));
            float d0, d1; unpack2(d2, d0, d1);
            float n0 = fminf(dist[2 * p], d0);
            float n1 = fminf(dist[2 * p + 1], d1);
            dist[2 * p] = n0;
            dist[2 * p + 1] = n1;
            bd = fmaxf(bd, n0);
            bd = fmaxf(bd, n1);
        }
        // recover lowest local index achieving bd (reverse scan -> lowest j wins)
        int bj = 0;
#pragma unroll
        for (int j = PPT - 1; j >= 0; j--) if (dist[j] == bd) bj = j;
        const int bi = base + bj;

        // warp argmax: dists >= 0 so float order == uint order on the bits
        const unsigned vb = __float_as_uint(bd);
        const unsigned wmax = redux_max_u32(vb);
        const unsigned cand = (vb == wmax) ? (unsigned)bi : 0xFFFFFFFFu;
        const unsigned wbi = redux_min_u32(cand);

        if (lane == 0)
            sm->key[par][w] = ((u64)wmax << 32) | (u64)wbi;
        __syncthreads();

        // stage 2: every warp redundantly reduces the 16 per-warp keys
        const u64 k = sm->key[par][lane & (NWARP - 1)];
        const unsigned kd = (unsigned)(k >> 32);
        const unsigned ki = (unsigned)k;
        const unsigned gmax = redux_max_u32(kd);
        const unsigned gc = (kd == gmax) ? ki : 0xFFFFFFFFu;
        f = (int)redux_min_u32(gc);

        par ^= 1;   // double-buffer: next iter's writes can't race this iter's reads
    }
}

// Output layout: [B,S,3] coords | [B,S,128] values | [B,S] mask, all fp32, concatenated.
__global__ void gather_kernel(const float* __restrict__ coords,
                              const float* __restrict__ values,
                              const float* __restrict__ mask,
                              float* __restrict__ out)
{
    const int V4 = BATCH * NSAMP * 32;   // float4 chunks of values output
    int i = blockIdx.x * blockDim.x + threadIdx.x;

    float* out_coords = out;
    float* out_vals   = out + (size_t)BATCH * NSAMP * 3;
    float* out_mask   = out + (size_t)BATCH * NSAMP * (3 + 128);

    if (i < V4) {
        const int c4 = i & 31;
        const int bs = i >> 5;
        const int b  = bs >> 12;
        const int s  = bs & (NSAMP - 1);
        const int idx = g_idx[b * NSAMP + s];
        const float4 v = reinterpret_cast<const float4*>(values)
                             [((size_t)b * NPTS + idx) * 32 + c4];
        reinterpret_cast<float4*>(out_vals)[(size_t)bs * 32 + c4] = v;
    } else if (i < V4 + BATCH * NSAMP) {
        const int bs = i - V4;
        const int b  = bs >> 12;
        const int s  = bs & (NSAMP - 1);
        const int idx = g_idx[b * NSAMP + s];
        const size_t src = (size_t)b * NPTS + idx;
        out_coords[bs * 3 + 0] = coords[src * 3 + 0];
        out_coords[bs * 3 + 1] = coords[src * 3 + 1];
        out_coords[bs * 3 + 2] = coords[src * 3 + 2];
        out_mask[bs] = mask[src];
    }
}

extern "C" void kernel_launch(void* const* d_in, const int* in_sizes, int n_in,
                              void* d_out, int out_size)
{
    const float* coords = (const float*)d_in[0];
    const float* values = (const float*)d_in[1];
    const float* mask   = (const float*)d_in[2];
    const int*   initf  = (const int*)d_in[3];
    float* out = (float*)d_out;

    const int smem = sizeof(SmemLayout);
    cudaFuncSetAttribute(fps_kernel, cudaFuncAttributeMaxDynamicSharedMemorySize, smem);

    fps_kernel<<<BATCH, THREADS, smem>>>(coords, initf);

    const int total = BATCH * NSAMP * 32 + BATCH * NSAMP;
    gather_kernel<<<(total + 255) / 256, 256>>>(coords, values, mask, out);
}